// round 1
// baseline (speedup 1.0000x reference)
#include <cuda_runtime.h>

#define TPB   128
#define ROUT  2
#define S_OUT (TPB*ROUT)   // 256 outputs per block
#define M     11
#define T     4096
#define BB    32

// A window per block: positions t0-20 .. t0+S_OUT-1  -> S_OUT+20 entries
// U window per block: positions t0-10 .. t0+S_OUT-1  -> S_OUT+10 entries
__global__ void __launch_bounds__(TPB)
gmp_kernel(const float2* __restrict__ x,
           const float*  __restrict__ W,
           float2* __restrict__ out)
{
    __shared__ float4 A4[S_OUT + 20];
    __shared__ float2 U  [S_OUT + 10];
    __shared__ float  ws [495];

    const int b   = blockIdx.y;
    const int t0  = blockIdx.x * S_OUT;
    const int tid = threadIdx.x;
    const float2* xb = x + (size_t)b * T;

    // Stage amplitude powers (a, a^2, a^3, a^4) and the complex samples.
    for (int j = tid; j < S_OUT + 20; j += TPB) {
        int pos = t0 + j - 20;
        float re = 0.f, im = 0.f;
        if (pos >= 0) { float2 v = xb[pos]; re = v.x; im = v.y; }
        float a2 = re * re + im * im;
        float a  = sqrtf(a2);
        A4[j] = make_float4(a, a2, a2 * a, a2 * a2);
        if (j >= 10) U[j - 10] = make_float2(re, im);
    }
    for (int j = tid; j < 495; j += TPB) ws[j] = W[j];
    __syncthreads();

    // This thread produces outputs t = t0 + 2*tid + {0,1}.
    // A positions needed: t-20 .. t (both outputs) -> shared idx 2*tid + [0,21]
    float4 Ar[22];
#pragma unroll
    for (int s = 0; s < 22; s++) Ar[s] = A4[2 * tid + s];
    // U positions needed: t-10 .. t -> shared idx 2*tid + [0,11]
    float2 Ur[12];
#pragma unroll
    for (int s = 0; s < 12; s++) Ur[s] = U[2 * tid + s];

    float ar0 = 0.f, ai0 = 0.f, ar1 = 0.f, ai1 = 0.f;

#pragma unroll
    for (int m = 0; m < M; m++) {
        float c0 = ws[m];
        float c1 = ws[m];
#pragma unroll
        for (int l = 0; l < M; l++) {
            const float4 p0 = Ar[m + l];       // A_k(t0q + m + l - 20), output r=0
            const float4 p1 = Ar[m + l + 1];   // output r=1
            float w;
            w = ws[11 + 0 * 121 + l * 11 + m]; c0 = fmaf(p0.x, w, c0); c1 = fmaf(p1.x, w, c1);
            w = ws[11 + 1 * 121 + l * 11 + m]; c0 = fmaf(p0.y, w, c0); c1 = fmaf(p1.y, w, c1);
            w = ws[11 + 2 * 121 + l * 11 + m]; c0 = fmaf(p0.z, w, c0); c1 = fmaf(p1.z, w, c1);
            w = ws[11 + 3 * 121 + l * 11 + m]; c0 = fmaf(p0.w, w, c0); c1 = fmaf(p1.w, w, c1);
        }
        // tap u(t + m - 10): shared idx (2*tid) + m for r=0, +1 for r=1
        ar0 = fmaf(Ur[m].x,     c0, ar0);  ai0 = fmaf(Ur[m].y,     c0, ai0);
        ar1 = fmaf(Ur[m + 1].x, c1, ar1);  ai1 = fmaf(Ur[m + 1].y, c1, ai1);
    }

    const int t = t0 + 2 * tid;
    float2* ob = out + (size_t)b * T;
    ob[t]     = make_float2(ar0, ai0);
    ob[t + 1] = make_float2(ar1, ai1);
}

extern "C" void kernel_launch(void* const* d_in, const int* in_sizes, int n_in,
                              void* d_out, int out_size)
{
    const float2* x = (const float2*)d_in[0];   // (32, 4096, 2) f32
    // d_in[1] = h_0 (unused by reference)
    const float*  W = (const float*)d_in[2];    // (1, 495) f32
    float2* out = (float2*)d_out;               // (32, 4096, 2) f32

    dim3 grid(T / S_OUT, BB);                   // (16, 32) = 512 blocks
    gmp_kernel<<<grid, TPB>>>(x, W, out);
}

// round 2
// speedup vs baseline: 1.1910x; 1.1910x over previous
#include <cuda_runtime.h>

#define TPB   128
#define R     2
#define S_OUT (TPB*R)        // 256 outputs per block
#define M     11
#define T     4096
#define BB    32
#define AW    (S_OUT + 20 + 2)   // 278, padded

__global__ void __launch_bounds__(TPB)
gmp_kernel(const float2* __restrict__ x,
           const float*  __restrict__ W,
           float2* __restrict__ out)
{
    __shared__ float  Ak[4][AW];       // amplitude powers, split per k (scalar arrays)
    __shared__ float2 U [S_OUT + 12];  // complex samples window
    __shared__ float  ws[495];

    const int b   = blockIdx.y;
    const int t0  = blockIdx.x * S_OUT;
    const int tid = threadIdx.x;
    const float2* xb = x + (size_t)b * T;

    // Stage: Ak[k][j] = |u(t0+j-20)|^(k+1),  U[i] = u(t0+i-10)
    for (int j = tid; j < S_OUT + 20; j += TPB) {
        int pos = t0 + j - 20;
        float re = 0.f, im = 0.f;
        if (pos >= 0) { float2 v = xb[pos]; re = v.x; im = v.y; }
        float a2 = re * re + im * im;
        float a  = sqrtf(a2);
        Ak[0][j] = a; Ak[1][j] = a2; Ak[2][j] = a2 * a; Ak[3][j] = a2 * a2;
        if (j >= 10) U[j - 10] = make_float2(re, im);
    }
    for (int j = tid; j < 495; j += TPB) ws[j] = W[j];
    __syncthreads();

    // Outputs t = t0 + 2*tid + r, r in {0,1}
    float c0[M], c1[M];
#pragma unroll
    for (int m = 0; m < M; m++) { c0[m] = ws[m]; c1[m] = ws[m]; }

#pragma unroll
    for (int k = 0; k < 4; k++) {
        // Scalar window of A_k: indices 2*tid + s, s = 0..21 used (load 24, 8B-aligned pairs)
        float win[24];
#pragma unroll
        for (int s = 0; s < 24; s += 2) {
            float2 v = *(const float2*)&Ak[k][tid * 2 + s];
            win[s] = v.x; win[s + 1] = v.y;
        }
        const float* wk = &ws[11 + k * 121];
#pragma unroll
        for (int l = 0; l < M; l++) {
#pragma unroll
            for (int m = 0; m < M; m++) {
                float w = wk[l * 11 + m];            // broadcast LDS
                c0[m] = fmaf(win[m + l],     w, c0[m]);
                c1[m] = fmaf(win[m + l + 1], w, c1[m]);
            }
        }
    }

    // Epilogue: out(t) = sum_m u(t+m-10) * c_m
    float2 ur[12];
#pragma unroll
    for (int s = 0; s < 12; s += 2) {
        float4 v = *(const float4*)&U[tid * 2 + s];   // 16B aligned
        ur[s]     = make_float2(v.x, v.y);
        ur[s + 1] = make_float2(v.z, v.w);
    }
    float ar0 = 0.f, ai0 = 0.f, ar1 = 0.f, ai1 = 0.f;
#pragma unroll
    for (int m = 0; m < M; m++) {
        ar0 = fmaf(ur[m].x,     c0[m], ar0);  ai0 = fmaf(ur[m].y,     c0[m], ai0);
        ar1 = fmaf(ur[m + 1].x, c1[m], ar1);  ai1 = fmaf(ur[m + 1].y, c1[m], ai1);
    }

    float4* ob = (float4*)(out + (size_t)b * T + t0) + tid;  // 16B aligned pair store
    *ob = make_float4(ar0, ai0, ar1, ai1);
}

extern "C" void kernel_launch(void* const* d_in, const int* in_sizes, int n_in,
                              void* d_out, int out_size)
{
    const float2* x = (const float2*)d_in[0];   // (32, 4096, 2) f32
    // d_in[1] = h_0 (unused by reference)
    const float*  W = (const float*)d_in[2];    // (1, 495) f32
    float2* out = (float2*)d_out;               // (32, 4096, 2) f32

    dim3 grid(T / S_OUT, BB);                   // (16, 32) = 512 blocks
    gmp_kernel<<<grid, TPB>>>(x, W, out);
}